// round 1
// baseline (speedup 1.0000x reference)
#include <cuda_runtime.h>
#include <math.h>

#define NN 100000
#define NE 3200000
#define D1 256
#define D2 64

// ---------------- static device scratch (no allocations allowed) ----------------
__device__ int   g_cnt[NN];
__device__ int   g_woff[NN];
__device__ int   g_rowptr[NN + 1];
__device__ int   g_col[NE];
__device__ float g_dinv1[NN];
__device__ float g_dinv2[NN];
__device__ float g_bufA[(size_t)NN * D1];
__device__ float g_bufB[(size_t)NN * D1];
__device__ float g_bufG[(size_t)NN * D2];

// ---------------- small helpers ----------------
__device__ __forceinline__ void fma4(float4& a, float w, const float4& v) {
    a.x = fmaf(w, v.x, a.x);
    a.y = fmaf(w, v.y, a.y);
    a.z = fmaf(w, v.z, a.z);
    a.w = fmaf(w, v.w, a.w);
}

__device__ __forceinline__ float selu_f(float x) {
    const float sc = 1.0507009873554804934f;
    const float al = 1.6732632423543772848f;
    return x > 0.f ? sc * x : sc * al * expm1f(x);
}

// ---------------- graph preprocessing ----------------
__global__ void k_clear(int n) {
    int i = blockIdx.x * blockDim.x + threadIdx.x;
    if (i < n) { g_cnt[i] = 0; g_woff[i] = 0; }
}

__global__ void k_count(const int* __restrict__ dst, int e) {
    int i = blockIdx.x * blockDim.x + threadIdx.x;
    if (i < e) atomicAdd(&g_cnt[dst[i]], 1);
}

__global__ void k_dinv(int n) {
    int i = blockIdx.x * blockDim.x + threadIdx.x;
    if (i < n) {
        int d = g_cnt[i];
        g_dinv1[i] = d > 0 ? rsqrtf((float)d) : 0.f;
        g_dinv2[i] = rsqrtf((float)(d + 1));
    }
}

// single-block exclusive scan of g_cnt -> g_rowptr (n up to 100000)
__global__ void k_scan(int n) {
    __shared__ int s[1024];
    int tid = threadIdx.x;
    int carry = 0;
    for (int base = 0; base < n; base += 1024) {
        int v = (base + tid < n) ? g_cnt[base + tid] : 0;
        s[tid] = v;
        __syncthreads();
        for (int off = 1; off < 1024; off <<= 1) {
            int t = (tid >= off) ? s[tid - off] : 0;
            __syncthreads();
            s[tid] += t;
            __syncthreads();
        }
        int incl = s[tid];
        if (base + tid < n) g_rowptr[base + tid] = carry + incl - v;
        int tot = s[1023];
        __syncthreads();
        carry += tot;
    }
    if (tid == 0) g_rowptr[n] = carry;
}

__global__ void k_fill(const int* __restrict__ src, const int* __restrict__ dst, int e) {
    int i = blockIdx.x * blockDim.x + threadIdx.x;
    if (i < e) {
        int d = dst[i];
        int p = g_rowptr[d] + atomicAdd(&g_woff[d], 1);
        g_col[p] = src[i];
    }
}

// ---------------- 256-dim propagation hop: out[i] = coeff*dinv[i]*sum_j dinv[c_j]*in[c_j] ----------------
__global__ void __launch_bounds__(256) k_hop256(
    const float* __restrict__ xin, float* __restrict__ xout,
    const float* __restrict__ dinv, const int* __restrict__ rowptr,
    const int* __restrict__ colidx, float coeff, int n)
{
    int node = (blockIdx.x * blockDim.x + threadIdx.x) >> 5;
    int lane = threadIdx.x & 31;
    if (node >= n) return;
    int beg = rowptr[node], end = rowptr[node + 1];

    float4 a0 = make_float4(0.f, 0.f, 0.f, 0.f);
    float4 a1 = make_float4(0.f, 0.f, 0.f, 0.f);

    for (int e0 = beg; e0 < end; e0 += 32) {
        int idx = e0 + lane;
        int c = 0; float w = 0.f;
        if (idx < end) { c = colidx[idx]; w = __ldg(dinv + c); }
        int cnt = min(32, end - e0);
        int j = 0;
        for (; j + 4 <= cnt; j += 4) {
            int   c0 = __shfl_sync(~0u, c, j + 0); float w0 = __shfl_sync(~0u, w, j + 0);
            int   c1 = __shfl_sync(~0u, c, j + 1); float w1 = __shfl_sync(~0u, w, j + 1);
            int   c2 = __shfl_sync(~0u, c, j + 2); float w2 = __shfl_sync(~0u, w, j + 2);
            int   c3 = __shfl_sync(~0u, c, j + 3); float w3 = __shfl_sync(~0u, w, j + 3);
            const float4* r0 = (const float4*)(xin + (size_t)c0 * D1);
            const float4* r1 = (const float4*)(xin + (size_t)c1 * D1);
            const float4* r2 = (const float4*)(xin + (size_t)c2 * D1);
            const float4* r3 = (const float4*)(xin + (size_t)c3 * D1);
            float4 v00 = __ldg(r0 + lane), v01 = __ldg(r0 + lane + 32);
            float4 v10 = __ldg(r1 + lane), v11 = __ldg(r1 + lane + 32);
            float4 v20 = __ldg(r2 + lane), v21 = __ldg(r2 + lane + 32);
            float4 v30 = __ldg(r3 + lane), v31 = __ldg(r3 + lane + 32);
            fma4(a0, w0, v00); fma4(a1, w0, v01);
            fma4(a0, w1, v10); fma4(a1, w1, v11);
            fma4(a0, w2, v20); fma4(a1, w2, v21);
            fma4(a0, w3, v30); fma4(a1, w3, v31);
        }
        for (; j < cnt; j++) {
            int   cj = __shfl_sync(~0u, c, j);
            float wj = __shfl_sync(~0u, w, j);
            const float4* r = (const float4*)(xin + (size_t)cj * D1);
            float4 v0 = __ldg(r + lane), v1 = __ldg(r + lane + 32);
            fma4(a0, wj, v0); fma4(a1, wj, v1);
        }
    }

    float s = coeff * __ldg(dinv + node);
    float4 o0 = make_float4(s * a0.x, s * a0.y, s * a0.z, s * a0.w);
    float4 o1 = make_float4(s * a1.x, s * a1.y, s * a1.z, s * a1.w);
    float4* orow = (float4*)(xout + (size_t)node * D1);
    orow[lane]      = o0;
    orow[lane + 32] = o1;
}

// ---------------- fp32 tiled GEMM: C[M,N] = act(A[M,256] @ B[256,N] (+bias)) ----------------
template<bool DO_SELU>
__global__ void __launch_bounds__(256) k_gemm(
    const float* __restrict__ A, const float* __restrict__ B,
    const float* __restrict__ bias, float* __restrict__ C, int M, int N)
{
    const int BM = 128, BN = 64, BK = 16;
    __shared__ float As[BK][BM];
    __shared__ float Bs[BK][BN];

    int tid  = threadIdx.x;
    int trow = tid & 15;   // rows trow*8 .. +7
    int tcol = tid >> 4;   // cols tcol*4 .. +3
    int blockM = blockIdx.x * BM;
    int blockN = blockIdx.y * BN;

    float acc[8][4];
#pragma unroll
    for (int i = 0; i < 8; i++)
#pragma unroll
        for (int j = 0; j < 4; j++) acc[i][j] = 0.f;

    for (int k0 = 0; k0 < 256; k0 += BK) {
        // A tile load: 128x16, transposed into As[k][m]
#pragma unroll
        for (int l = 0; l < 2; l++) {
            int pos = tid * 2 + l;          // 0..511
            int r  = pos >> 2;              // row in tile 0..127
            int cv = pos & 3;               // which float4 in the 16-col slab
            int gr = blockM + r;
            if (gr > M - 1) gr = M - 1;
            float4 v = *(const float4*)(A + (size_t)gr * 256 + k0 + cv * 4);
            As[cv * 4 + 0][r] = v.x;
            As[cv * 4 + 1][r] = v.y;
            As[cv * 4 + 2][r] = v.z;
            As[cv * 4 + 3][r] = v.w;
        }
        // B tile load: 16x64
        {
            int r = tid >> 4;               // 0..15
            int cb = (tid & 15) * 4;        // 0..60
            float4 v = *(const float4*)(B + (size_t)(k0 + r) * N + blockN + cb);
            *(float4*)&Bs[r][cb] = v;
        }
        __syncthreads();
#pragma unroll
        for (int k = 0; k < BK; k++) {
            float a[8], b[4];
#pragma unroll
            for (int i = 0; i < 8; i++) a[i] = As[k][trow * 8 + i];
#pragma unroll
            for (int j = 0; j < 4; j++) b[j] = Bs[k][tcol * 4 + j];
#pragma unroll
            for (int i = 0; i < 8; i++)
#pragma unroll
                for (int j = 0; j < 4; j++) acc[i][j] = fmaf(a[i], b[j], acc[i][j]);
        }
        __syncthreads();
    }

    float4 bias4 = make_float4(0.f, 0.f, 0.f, 0.f);
    if (DO_SELU) bias4 = *(const float4*)(bias + blockN + tcol * 4);

#pragma unroll
    for (int i = 0; i < 8; i++) {
        int gr = blockM + trow * 8 + i;
        if (gr < M) {
            float4 v;
            if (DO_SELU) {
                v.x = selu_f(acc[i][0] + bias4.x);
                v.y = selu_f(acc[i][1] + bias4.y);
                v.z = selu_f(acc[i][2] + bias4.z);
                v.w = selu_f(acc[i][3] + bias4.w);
            } else {
                v.x = acc[i][0]; v.y = acc[i][1]; v.z = acc[i][2]; v.w = acc[i][3];
            }
            *(float4*)(C + (size_t)gr * N + blockN + tcol * 4) = v;
        }
    }
}

// ---------------- final hop (D=64, self loops) + bias + log_softmax ----------------
__global__ void __launch_bounds__(256) k_out(
    const float* __restrict__ g, const float* __restrict__ dinv2,
    const int* __restrict__ rowptr, const int* __restrict__ colidx,
    const float* __restrict__ b2, float* __restrict__ out, int n)
{
    int node = (blockIdx.x * blockDim.x + threadIdx.x) >> 5;
    int lane = threadIdx.x & 31;
    if (node >= n) return;
    int beg = rowptr[node], end = rowptr[node + 1];

    float di = __ldg(dinv2 + node);
    // self loop term
    float2 sv = __ldg((const float2*)(g + (size_t)node * D2) + lane);
    float ax = di * sv.x;
    float ay = di * sv.y;

    for (int e0 = beg; e0 < end; e0 += 32) {
        int idx = e0 + lane;
        int c = 0; float w = 0.f;
        if (idx < end) { c = colidx[idx]; w = __ldg(dinv2 + c); }
        int cnt = min(32, end - e0);
        int j = 0;
        for (; j + 4 <= cnt; j += 4) {
            int   c0 = __shfl_sync(~0u, c, j + 0); float w0 = __shfl_sync(~0u, w, j + 0);
            int   c1 = __shfl_sync(~0u, c, j + 1); float w1 = __shfl_sync(~0u, w, j + 1);
            int   c2 = __shfl_sync(~0u, c, j + 2); float w2 = __shfl_sync(~0u, w, j + 2);
            int   c3 = __shfl_sync(~0u, c, j + 3); float w3 = __shfl_sync(~0u, w, j + 3);
            float2 v0 = __ldg((const float2*)(g + (size_t)c0 * D2) + lane);
            float2 v1 = __ldg((const float2*)(g + (size_t)c1 * D2) + lane);
            float2 v2 = __ldg((const float2*)(g + (size_t)c2 * D2) + lane);
            float2 v3 = __ldg((const float2*)(g + (size_t)c3 * D2) + lane);
            ax = fmaf(w0, v0.x, ax); ay = fmaf(w0, v0.y, ay);
            ax = fmaf(w1, v1.x, ax); ay = fmaf(w1, v1.y, ay);
            ax = fmaf(w2, v2.x, ax); ay = fmaf(w2, v2.y, ay);
            ax = fmaf(w3, v3.x, ax); ay = fmaf(w3, v3.y, ay);
        }
        for (; j < cnt; j++) {
            int   cj = __shfl_sync(~0u, c, j);
            float wj = __shfl_sync(~0u, w, j);
            float2 v = __ldg((const float2*)(g + (size_t)cj * D2) + lane);
            ax = fmaf(wj, v.x, ax); ay = fmaf(wj, v.y, ay);
        }
    }

    float p0 = di * ax + __ldg(b2 + lane * 2);
    float p1 = di * ay + __ldg(b2 + lane * 2 + 1);

    // warp log-softmax over 64 values
    float m = fmaxf(p0, p1);
#pragma unroll
    for (int o = 16; o; o >>= 1) m = fmaxf(m, __shfl_xor_sync(~0u, m, o));
    float esum = expf(p0 - m) + expf(p1 - m);
#pragma unroll
    for (int o = 16; o; o >>= 1) esum += __shfl_xor_sync(~0u, esum, o);
    float lse = m + logf(esum);

    float2 res = make_float2(p0 - lse, p1 - lse);
    ((float2*)(out + (size_t)node * D2))[lane] = res;
}

// ---------------- launch ----------------
extern "C" void kernel_launch(void* const* d_in, const int* in_sizes, int n_in,
                              void* d_out, int out_size) {
    const float* x    = (const float*)d_in[0];
    const int*   esrc = (const int*)d_in[1];
    const int*   edst = (const int*)d_in[2];
    const float* W1   = (const float*)d_in[3];
    const float* b1   = (const float*)d_in[4];
    const float* W2   = (const float*)d_in[5];
    const float* b2   = (const float*)d_in[6];
    float* out = (float*)d_out;

    int n = in_sizes[0] / D1;   // 100000
    int e = in_sizes[1];        // 3200000

    float *bufA, *bufB, *bufG, *dinv1, *dinv2;
    int *rowptr, *colidx;
    cudaGetSymbolAddress((void**)&bufA, g_bufA);
    cudaGetSymbolAddress((void**)&bufB, g_bufB);
    cudaGetSymbolAddress((void**)&bufG, g_bufG);
    cudaGetSymbolAddress((void**)&dinv1, g_dinv1);
    cudaGetSymbolAddress((void**)&dinv2, g_dinv2);
    cudaGetSymbolAddress((void**)&rowptr, g_rowptr);
    cudaGetSymbolAddress((void**)&colidx, g_col);

    int nb = (n + 255) / 256;
    int eb = (e + 255) / 256;
    int hopBlocks = (n * 32 + 255) / 256;

    // CSR build + normalization
    k_clear<<<nb, 256>>>(n);
    k_count<<<eb, 256>>>(edst, e);
    k_dinv<<<nb, 256>>>(n);
    k_scan<<<1, 1024>>>(n);
    k_fill<<<eb, 256>>>(esrc, edst, e);

    // conv1: two hops (coeff 1, exp(-1)), then Linear+SELU
    k_hop256<<<hopBlocks, 256>>>(x,    bufA, dinv1, rowptr, colidx, 1.0f, n);
    k_hop256<<<hopBlocks, 256>>>(bufA, bufB, dinv1, rowptr, colidx, 0.36787944117144233f, n);

    dim3 g1((n + 127) / 128, 2);  // N=256 -> 4 col-tiles of 64
    g1.y = 4;
    k_gemm<true><<<g1, 256>>>(bufB, W1, b1, bufA, n, 256);

    // conv2 reordered: g = h @ W2 first (64-dim), then 1 hop w/ self loops + b2 + log_softmax
    dim3 g2((n + 127) / 128, 1);
    k_gemm<false><<<g2, 256>>>(bufA, W2, nullptr, bufG, n, 64);

    k_out<<<hopBlocks, 256>>>(bufG, dinv2, rowptr, colidx, b2, out, n);
}